// round 16
// baseline (speedup 1.0000x reference)
#include <cuda_runtime.h>
#include <cuda_bf16.h>
#include <math.h>
#include <stdint.h>

// Problem constants
#define Bc   2
#define Qn   4096
#define Kn   4096
#define DQ   512
#define NH   8
#define DH   32
#define INNER (NH*DH)   // 256

// ---------------- scratch (no allocs allowed) ----------------
// packed bf16 hi/lo planes: one uint32 = 2 adjacent-d bf16 values
__device__ unsigned g_qh[Bc*Qn*128], g_ql[Bc*Qn*128];    // q * scaling*log2e
__device__ unsigned g_kh[Bc*Kn*128], g_kl[Bc*Kn*128];
__device__ unsigned g_vph[Bc*Kn*128], g_vpl[Bc*Kn*128];  // V planar (d-paired)
__device__ unsigned g_vh[Bc*NH*(Kn/2)*32], g_vl[Bc*NH*(Kn/2)*32]; // V k-paired
__device__ float    g_qo[Bc*Qn*INNER];  // attention out (pre Wo)
__device__ float    g_qn[Bc*NH*Qn];     // ||q_row|| (log2-domain)
__device__ float    g_knm[Bc*NH];       // max_k ||k_row||

// ================= mma.sync bf16 plumbing (sm_80+, no 'a' features) ========
__device__ __forceinline__ void mma_bf16(float c[4], const uint32_t a[4],
                                         const uint32_t b[2]) {
    asm volatile(
        "mma.sync.aligned.m16n8k16.row.col.f32.bf16.bf16.f32 "
        "{%0,%1,%2,%3}, {%4,%5,%6,%7}, {%8,%9}, {%0,%1,%2,%3};"
        : "+f"(c[0]), "+f"(c[1]), "+f"(c[2]), "+f"(c[3])
        : "r"(a[0]), "r"(a[1]), "r"(a[2]), "r"(a[3]), "r"(b[0]), "r"(b[1]));
}

__device__ __forceinline__ uint32_t bfpack(float x, float y) {
    __nv_bfloat162 t;
    t.x = __float2bfloat16(x);
    t.y = __float2bfloat16(y);
    return *(uint32_t*)&t;
}
__device__ __forceinline__ float bfhi(float x) {
    return __bfloat162float(__float2bfloat16(x));
}
__device__ __forceinline__ float ex2(float x) {
    float r;
    asm("ex2.approx.f32 %0, %1;" : "=f"(r) : "f"(x));
    return r;
}
__device__ __forceinline__ float2 up2(unsigned u) {
    __nv_bfloat162 t = *reinterpret_cast<__nv_bfloat162*>(&u);
    return make_float2(__bfloat162float(t.x), __bfloat162float(t.y));
}

// ---------------- tensor-core GEMM, bf16x3 ----------------------------------
// PACKED=0: C = scale*(A@W)+bias (fp32 out). PACKED=1: writes bf16 hi/lo planes.
#define G_AH 0
#define G_AL 2176
#define G_BH 4352
#define G_BL 6528
#define G_WORDS 8704

template<int PACKED>
__global__ void __launch_bounds__(256)
gemm_tc(const float* __restrict__ A, const float* __restrict__ W,
        const float* __restrict__ bias, float* __restrict__ C,
        unsigned* __restrict__ Ch, unsigned* __restrict__ Cl,
        int M, int N, int K, float scale) {
    __shared__ float sm[G_WORDS];
    uint32_t* ahw = (uint32_t*)(sm + G_AH);
    uint32_t* alw = (uint32_t*)(sm + G_AL);
    uint32_t* bhw = (uint32_t*)(sm + G_BH);
    uint32_t* blw = (uint32_t*)(sm + G_BL);

    const int bm = blockIdx.x * 128, bn = blockIdx.y * 128;
    const int tid = threadIdx.x;
    const int warp = tid >> 5, lane = tid & 31;
    const int g = lane >> 2, qd = lane & 3;
    const int r0 = warp * 16 + g;

    float o[16][4];
#pragma unroll
    for (int nt = 0; nt < 16; nt++)
#pragma unroll
        for (int j = 0; j < 4; j++) o[nt][j] = 0.f;

    for (int k0 = 0; k0 < K; k0 += 32) {
        __syncthreads();
#pragma unroll
        for (int i = 0; i < 8; i++) {
            int idx = tid + i * 256;
            int wp = idx >> 7, r = idx & 127;
            float2 v = *(const float2*)&A[(size_t)(bm + r) * K + k0 + 2 * wp];
            float h0 = bfhi(v.x), h1 = bfhi(v.y);
            ahw[wp * 136 + r] = bfpack(h0, h1);
            alw[wp * 136 + r] = bfpack(v.x - h0, v.y - h1);
        }
#pragma unroll
        for (int i = 0; i < 8; i++) {
            int idx = tid + i * 256;
            int wp = idx >> 7, n = idx & 127;
            float x0 = W[(size_t)(k0 + 2 * wp) * N + bn + n];
            float x1 = W[(size_t)(k0 + 2 * wp + 1) * N + bn + n];
            float h0 = bfhi(x0), h1 = bfhi(x1);
            bhw[wp * 136 + n] = bfpack(h0, h1);
            blw[wp * 136 + n] = bfpack(x0 - h0, x1 - h1);
        }
        __syncthreads();

        uint32_t aH[2][4], aL[2][4];
#pragma unroll
        for (int kst = 0; kst < 2; kst++) {
            int ba = (kst * 8 + qd) * 136 + r0;
            aH[kst][0] = ahw[ba];            aH[kst][1] = ahw[ba + 8];
            aH[kst][2] = ahw[ba + 4 * 136];  aH[kst][3] = ahw[ba + 4 * 136 + 8];
            aL[kst][0] = alw[ba];            aL[kst][1] = alw[ba + 8];
            aL[kst][2] = alw[ba + 4 * 136];  aL[kst][3] = alw[ba + 4 * 136 + 8];
        }
#pragma unroll
        for (int nt = 0; nt < 16; nt++) {
#pragma unroll
            for (int kst = 0; kst < 2; kst++) {
                uint32_t bH[2], bL[2];
                int ba = (kst * 8 + qd) * 136 + nt * 8 + g;
                bH[0] = bhw[ba]; bH[1] = bhw[ba + 4 * 136];
                bL[0] = blw[ba]; bL[1] = blw[ba + 4 * 136];
                mma_bf16(o[nt], aH[kst], bH);
                mma_bf16(o[nt], aH[kst], bL);
                mma_bf16(o[nt], aL[kst], bH);
            }
        }
    }

    // epilogue
#pragma unroll
    for (int nt = 0; nt < 16; nt++) {
        if (PACKED) {
            int colp = ((bn + nt * 8) >> 1) + qd;   // uint32-pair index
            float x0 = o[nt][0] * scale, x1 = o[nt][1] * scale;
            float h0 = bfhi(x0), h1 = bfhi(x1);
            size_t d0 = (size_t)(bm + r0) * (N >> 1) + colp;
            Ch[d0] = bfpack(h0, h1);
            Cl[d0] = bfpack(x0 - h0, x1 - h1);
            float x2 = o[nt][2] * scale, x3 = o[nt][3] * scale;
            float h2 = bfhi(x2), h3 = bfhi(x3);
            size_t d1 = (size_t)(bm + r0 + 8) * (N >> 1) + colp;
            Ch[d1] = bfpack(h2, h3);
            Cl[d1] = bfpack(x2 - h2, x3 - h3);
        } else {
            int col = bn + nt * 8 + qd * 2;
            float b0 = 0.f, b1 = 0.f;
            if (bias) { b0 = bias[col]; b1 = bias[col + 1]; }
            *(float2*)&C[(size_t)(bm + r0) * N + col] =
                make_float2(o[nt][0] * scale + b0, o[nt][1] * scale + b1);
            *(float2*)&C[(size_t)(bm + r0 + 8) * N + col] =
                make_float2(o[nt][2] * scale + b0, o[nt][3] * scale + b1);
        }
    }
}

// ---------------- V repack: planar (d-paired) -> k-paired -------------------
__global__ void repackv_kernel(const unsigned* __restrict__ vph,
                               const unsigned* __restrict__ vpl,
                               unsigned* __restrict__ vh, unsigned* __restrict__ vl) {
    int t = blockIdx.x * 256 + threadIdx.x;   // 524288
    int dp = t & 15;
    int kp = (t >> 4) & 2047;
    int h  = (t >> 15) & 7;
    int b  = t >> 18;
    size_t s0 = ((size_t)(b * Kn) + 2 * kp) * 128 + h * 16 + dp;
    size_t d  = ((size_t)(b * NH + h) * 2048 + kp) * 32 + 2 * dp;
    unsigned a0 = vph[s0], a1 = vph[s0 + 128], o0, o1;
    asm("prmt.b32 %0, %1, %2, 0x5410;" : "=r"(o0) : "r"(a0), "r"(a1));
    asm("prmt.b32 %0, %1, %2, 0x7632;" : "=r"(o1) : "r"(a0), "r"(a1));
    vh[d] = o0; vh[d + 1] = o1;
    a0 = vpl[s0]; a1 = vpl[s0 + 128];
    asm("prmt.b32 %0, %1, %2, 0x5410;" : "=r"(o0) : "r"(a0), "r"(a1));
    asm("prmt.b32 %0, %1, %2, 0x7632;" : "=r"(o1) : "r"(a0), "r"(a1));
    vl[d] = o0; vl[d + 1] = o1;
}

// ---------------- norm kernels (read packed, reconstruct hi+lo) -------------
__global__ void qnorm_kernel(const unsigned* __restrict__ qh,
                             const unsigned* __restrict__ ql, float* __restrict__ qn) {
    int t = blockIdx.x * 256 + threadIdx.x;
    int h = t & 7, bq = t >> 3;
    int b = bq >> 12, qq = bq & 4095;
    const unsigned* ph = qh + (size_t)bq * 128 + h * 16;
    const unsigned* pl = ql + (size_t)bq * 128 + h * 16;
    float s = 0.f;
#pragma unroll
    for (int wp = 0; wp < 16; wp++) {
        float2 hi = up2(ph[wp]), lo = up2(pl[wp]);
        float x = hi.x + lo.x, y = hi.y + lo.y;
        s += x * x + y * y;
    }
    qn[((b * NH + h) * Qn) + qq] = sqrtf(s);
}

__global__ void knorm_kernel(const unsigned* __restrict__ kh,
                             const unsigned* __restrict__ kl, float* __restrict__ knm) {
    int bh = blockIdx.x;
    int b = bh >> 3, h = bh & 7;
    float mx = 0.f;
    for (int row = threadIdx.x; row < Kn; row += 256) {
        const unsigned* ph = kh + (size_t)(b * Kn + row) * 128 + h * 16;
        const unsigned* pl = kl + (size_t)(b * Kn + row) * 128 + h * 16;
        float s = 0.f;
#pragma unroll
        for (int wp = 0; wp < 16; wp++) {
            float2 hi = up2(ph[wp]), lo = up2(pl[wp]);
            float x = hi.x + lo.x, y = hi.y + lo.y;
            s += x * x + y * y;
        }
        mx = fmaxf(mx, s);
    }
    __shared__ float red[256];
    red[threadIdx.x] = mx;
    __syncthreads();
    for (int s = 128; s; s >>= 1) {
        if (threadIdx.x < s) red[threadIdx.x] = fmaxf(red[threadIdx.x], red[threadIdx.x + s]);
        __syncthreads();
    }
    if (threadIdx.x == 0) knm[bh] = sqrtf(red[0]);
}

// ---------------- single-pass fused attention (packed operands) -------------
// K/V smem layouts pair fragment words (wp, wp+4) adjacently -> LDS.64.
//   K: khw2[pr*264 + col*2 + sub], pr = (wp&3)|((wp>>3)<<2), sub = (wp>>2)&1
//   V: vhw [pr*72  + d*2   + sub], pr = (kp&3)|((kp>>3)<<2), sub = (kp>>2)&1
#define S_QH 0        // [16 wp][128 r] stride 136
#define S_QL 2176
#define S_KH 4352     // 8 pr x 264
#define S_KL 6464
#define S_VH 8576     // 32 pr x 72
#define S_VL 10880
#define S_IL 13184
#define SM_WORDS 13312
#define SM_BYTES (SM_WORDS*4)   // 53248

__global__ void __launch_bounds__(256, 2)
fa_kernel(const unsigned* __restrict__ qh, const unsigned* __restrict__ ql,
          const unsigned* __restrict__ kh, const unsigned* __restrict__ kl,
          const unsigned* __restrict__ vh, const unsigned* __restrict__ vl,
          const float* __restrict__ qn, const float* __restrict__ knm,
          float* __restrict__ wout, float* __restrict__ qo) {
    extern __shared__ float sm[];
    uint32_t* qhw  = (uint32_t*)(sm + S_QH);
    uint32_t* qlw  = (uint32_t*)(sm + S_QL);
    uint32_t* khw2 = (uint32_t*)(sm + S_KH);
    uint32_t* klw2 = (uint32_t*)(sm + S_KL);
    uint32_t* vhw  = (uint32_t*)(sm + S_VH);
    uint32_t* vlw  = (uint32_t*)(sm + S_VL);
    float*    ilm  = sm + S_IL;

    const int b = blockIdx.z, h = blockIdx.y, q0 = blockIdx.x * 128;
    const int tid = threadIdx.x;
    const int warp = tid >> 5, lane = tid & 31;
    const int g = lane >> 2, qd = lane & 3;
    const size_t bh = (size_t)(b * NH + h);

    // ---- stage Q tile (pure copy of packed planes) ----
#pragma unroll
    for (int i = 0; i < 8; i++) {
        int idx = tid + i * 256;
        int wp = idx >> 7, r = idx & 127;
        size_t gs = ((size_t)(b * Qn) + q0 + r) * 128 + h * 16 + wp;
        qhw[wp * 136 + r] = qh[gs];
        qlw[wp * 136 + r] = ql[gs];
    }

    const int r0 = warp * 16 + g;
    float cp0, cp1;
    {
        float km = knm[bh];
        cp0 = qn[bh * Qn + q0 + r0] * km;
        cp1 = qn[bh * Qn + q0 + r0 + 8] * km;
    }
    float l0 = 0.f, l1 = 0.f;

    __syncthreads();

    // ---- Q A-fragments (persist whole kernel) ----
    uint32_t aH[2][4], aL[2][4];
#pragma unroll
    for (int kst = 0; kst < 2; kst++) {
        int ba = (kst * 8 + qd) * 136 + warp * 16 + g;
        aH[kst][0] = qhw[ba];            aH[kst][1] = qhw[ba + 8];
        aH[kst][2] = qhw[ba + 4 * 136];  aH[kst][3] = qhw[ba + 4 * 136 + 8];
        aL[kst][0] = qlw[ba];            aL[kst][1] = qlw[ba + 8];
        aL[kst][2] = qlw[ba + 4 * 136];  aL[kst][3] = qlw[ba + 4 * 136 + 8];
    }

    float o[4][4];
#pragma unroll
    for (int dt = 0; dt < 4; dt++)
#pragma unroll
        for (int j = 0; j < 4; j++) o[dt][j] = 0.f;

    for (int c = 0; c < Kn / 128; c++) {
        const int c0 = c * 128;
        __syncthreads();

        // ---- stage K chunk (copy into paired layout) ----
#pragma unroll
        for (int i = 0; i < 8; i++) {
            int idx = tid + i * 256;
            int wp = idx >> 7, col = idx & 127;
            int pr = (wp & 3) | ((wp >> 3) << 2), sub = (wp >> 2) & 1;
            size_t gs = ((size_t)(b * Kn) + c0 + col) * 128 + h * 16 + wp;
            khw2[pr * 264 + col * 2 + sub] = kh[gs];
            klw2[pr * 264 + col * 2 + sub] = kl[gs];
        }
        // ---- stage V chunk (coalesced copy into paired layout) ----
#pragma unroll
        for (int i = 0; i < 8; i++) {
            int idx = tid + i * 256;
            int kp = idx >> 5, d = idx & 31;
            int pr = (kp & 3) | ((kp >> 3) << 2), sub = (kp >> 2) & 1;
            size_t gs = (bh * 2048 + (c0 >> 1) + kp) * 32 + d;
            vhw[pr * 72 + d * 2 + sub] = vh[gs];
            vlw[pr * 72 + d * 2 + sub] = vl[gs];
        }
        __syncthreads();

#pragma unroll 2
        for (int ksb = 0; ksb < 8; ksb++) {
            uint32_t pH[4], pL[4];
#pragma unroll
            for (int t = 0; t < 2; t++) {
                const int nt = ksb * 2 + t;
                float cacc[4] = {0.f, 0.f, 0.f, 0.f};
#pragma unroll
                for (int kst = 0; kst < 2; kst++) {
                    int ba = (kst * 4 + qd) * 264 + (nt * 8 + g) * 2;
                    uint2 bh2 = *(const uint2*)&khw2[ba];
                    uint2 bl2 = *(const uint2*)&klw2[ba];
                    uint32_t bH[2] = {bh2.x, bh2.y};
                    uint32_t bL[2] = {bl2.x, bl2.y};
                    mma_bf16(cacc, aH[kst], bH);
                    mma_bf16(cacc, aH[kst], bL);
                    mma_bf16(cacc, aL[kst], bH);
                }
                float p0 = ex2(cacc[0] - cp0);
                float p1 = ex2(cacc[1] - cp0);
                float p2 = ex2(cacc[2] - cp1);
                float p3 = ex2(cacc[3] - cp1);
                l0 += p0 + p1;
                l1 += p2 + p3;
                size_t wb = (bh * Qn + q0 + r0) * (size_t)Kn + c0 + nt * 8 + qd * 2;
                *(float2*)&wout[wb] = make_float2(p0, p1);
                *(float2*)&wout[wb + (size_t)8 * Kn] = make_float2(p2, p3);
                float h0 = bfhi(p0), h1 = bfhi(p1);
                float h2 = bfhi(p2), h3 = bfhi(p3);
                pH[2 * t + 0] = bfpack(h0, h1);
                pH[2 * t + 1] = bfpack(h2, h3);
                pL[2 * t + 0] = bfpack(p0 - h0, p1 - h1);
                pL[2 * t + 1] = bfpack(p2 - h2, p3 - h3);
            }
            // ---- PV ----
#pragma unroll
            for (int dt = 0; dt < 4; dt++) {
                int ba = (ksb * 4 + qd) * 72 + (dt * 8 + g) * 2;
                uint2 vh2 = *(const uint2*)&vhw[ba];
                uint2 vl2 = *(const uint2*)&vlw[ba];
                uint32_t bH[2] = {vh2.x, vh2.y};
                uint32_t bL[2] = {vl2.x, vl2.y};
                mma_bf16(o[dt], pH, bH);
                mma_bf16(o[dt], pH, bL);
                mma_bf16(o[dt], pL, bH);
            }
        }
    }

    // ---- reduce l, normalize O, share 1/l ----
    l0 += __shfl_xor_sync(0xffffffffu, l0, 1);
    l0 += __shfl_xor_sync(0xffffffffu, l0, 2);
    l1 += __shfl_xor_sync(0xffffffffu, l1, 1);
    l1 += __shfl_xor_sync(0xffffffffu, l1, 2);
    float il0 = 1.0f / l0, il1 = 1.0f / l1;
    if (qd == 0) {
        ilm[r0] = il0;
        ilm[r0 + 8] = il1;
    }
    float* op0 = qo + ((size_t)(b * Qn) + q0 + r0) * INNER + h * DH;
    float* op1 = qo + ((size_t)(b * Qn) + q0 + r0 + 8) * INNER + h * DH;
#pragma unroll
    for (int dt = 0; dt < 4; dt++) {
        *(float2*)&op0[dt * 8 + qd * 2] = make_float2(o[dt][0] * il0, o[dt][1] * il0);
        *(float2*)&op1[dt * 8 + qd * 2] = make_float2(o[dt][2] * il1, o[dt][3] * il1);
    }
    __syncthreads();   // orders this CTA's weight STGs + ilm before re-read

    // ---- fused normalize of this CTA's contiguous 2MB weights tile ----
    {
        float* wt = wout + (bh * Qn + q0) * (size_t)Kn;
        for (int i = tid; i < 128 * 1024; i += 256) {
            float il = ilm[i >> 10];
            float4 v = *(float4*)&wt[(size_t)i * 4];
            v.x *= il; v.y *= il; v.z *= il; v.w *= il;
            *(float4*)&wt[(size_t)i * 4] = v;
        }
    }
}

// ---------------- launch ----------------
extern "C" void kernel_launch(void* const* d_in, const int* in_sizes, int n_in,
                              void* d_out, int out_size) {
    const float* query = (const float*)d_in[0];
    const float* key   = (const float*)d_in[1];
    const float* value = (const float*)d_in[2];
    const float* Wq    = (const float*)d_in[3];
    const float* Wk    = (const float*)d_in[4];
    const float* Wv    = (const float*)d_in[5];
    const float* Wo    = (const float*)d_in[6];
    const float* bo    = (const float*)d_in[7];

    float* out_attn = (float*)d_out;                       // [B,Q,512]
    float* out_w    = (float*)d_out + (size_t)Bc*Qn*DQ;    // [B,H,Q,K]

    unsigned *qhp, *qlp, *khp, *klp, *vphp, *vplp, *vhp, *vlp;
    float *qop, *qnp, *knp;
    cudaGetSymbolAddress((void**)&qhp,  g_qh);
    cudaGetSymbolAddress((void**)&qlp,  g_ql);
    cudaGetSymbolAddress((void**)&khp,  g_kh);
    cudaGetSymbolAddress((void**)&klp,  g_kl);
    cudaGetSymbolAddress((void**)&vphp, g_vph);
    cudaGetSymbolAddress((void**)&vplp, g_vpl);
    cudaGetSymbolAddress((void**)&vhp,  g_vh);
    cudaGetSymbolAddress((void**)&vlp,  g_vl);
    cudaGetSymbolAddress((void**)&qop,  g_qo);
    cudaGetSymbolAddress((void**)&qnp,  g_qn);
    cudaGetSymbolAddress((void**)&knp,  g_knm);

    const int M = Bc * Qn;          // 8192
    // 1/sqrt(32) * log2(e): scores land in log2 domain -> ex2 in fa_kernel
    const float scaling = 0.17677669529663687f * 1.4426950408889634f;

    // 1) projections -> packed bf16 hi/lo planes (tensor cores, bf16x3)
    {
        dim3 grid(M / 128, INNER / 128);
        gemm_tc<1><<<grid, 256>>>(query, Wq, nullptr, nullptr, qhp,  qlp,  M, INNER, DQ, scaling);
        gemm_tc<1><<<grid, 256>>>(key,   Wk, nullptr, nullptr, khp,  klp,  M, INNER, DQ, 1.f);
        gemm_tc<1><<<grid, 256>>>(value, Wv, nullptr, nullptr, vphp, vplp, M, INNER, DQ, 1.f);
    }
    // 2) V repack (d-paired -> k-paired) + softmax shift bound
    {
        repackv_kernel<<<2048, 256>>>(vphp, vplp, vhp, vlp);
        qnorm_kernel<<<Bc * Qn * NH / 256, 256>>>(qhp, qlp, qnp);
        knorm_kernel<<<Bc * NH, 256>>>(khp, klp, knp);
    }
    // 3) single-pass attention + fused in-place weight normalize
    {
        cudaFuncSetAttribute(fa_kernel, cudaFuncAttributeMaxDynamicSharedMemorySize, SM_BYTES);
        dim3 grid(Qn / 128, NH, Bc);
        fa_kernel<<<grid, 256, SM_BYTES>>>(qhp, qlp, khp, klp, vhp, vlp,
                                           qnp, knp, out_w, qop);
    }
    // 4) output projection + bias (fp32 out)
    {
        dim3 grid(M / 128, DQ / 128);
        gemm_tc<0><<<grid, 256>>>(qop, Wo, bo, out_attn, nullptr, nullptr,
                                  M, DQ, INNER, 1.f);
    }
}

// round 17
// speedup vs baseline: 1.5882x; 1.5882x over previous
#include <cuda_runtime.h>
#include <cuda_bf16.h>
#include <math.h>
#include <stdint.h>

// Problem constants
#define Bc   2
#define Qn   4096
#define Kn   4096
#define DQ   512
#define NH   8
#define DH   32
#define INNER (NH*DH)   // 256

// ---------------- scratch (no allocs allowed) ----------------
__device__ float g_qs[Bc*Qn*INNER];   // projected q * scaling * log2e  [B,Q,256]
__device__ float g_ks[Bc*Kn*INNER];   // projected k          [B,K,256]
__device__ float g_vs[Bc*Kn*INNER];   // projected v          [B,K,256]
__device__ float g_qo[Bc*Qn*INNER];   // attention out (pre Wo) [B,Q,256]
__device__ float g_qn[Bc*NH*Qn];      // ||q_row|| (log2-domain) -> shift c
__device__ float g_knm[Bc*NH];        // max_k ||k_row||

// ================= mma.sync bf16 plumbing (sm_80+, no 'a' features) ========
__device__ __forceinline__ void mma_bf16(float c[4], const uint32_t a[4],
                                         const uint32_t b[2]) {
    asm volatile(
        "mma.sync.aligned.m16n8k16.row.col.f32.bf16.bf16.f32 "
        "{%0,%1,%2,%3}, {%4,%5,%6,%7}, {%8,%9}, {%0,%1,%2,%3};"
        : "+f"(c[0]), "+f"(c[1]), "+f"(c[2]), "+f"(c[3])
        : "r"(a[0]), "r"(a[1]), "r"(a[2]), "r"(a[3]), "r"(b[0]), "r"(b[1]));
}

__device__ __forceinline__ uint32_t bfpack(float x, float y) {
    __nv_bfloat162 t;
    t.x = __float2bfloat16(x);
    t.y = __float2bfloat16(y);
    return *(uint32_t*)&t;
}
__device__ __forceinline__ float bfhi(float x) {
    return __bfloat162float(__float2bfloat16(x));
}
// fast base-2 exp via MUFU.EX2 (single SASS instruction)
__device__ __forceinline__ float ex2(float x) {
    float r;
    asm("ex2.approx.f32 %0, %1;" : "=f"(r) : "f"(x));
    return r;
}

// ---------------- tensor-core GEMM, bf16x3: C = scale*(A@W) (+bias) --------
// A[M,K] row-major, W[K,N] row-major, C[M,N]. Tile 128x128, 256 thr, 8 warps.
#define G_AH 0        // [16 kd-pairs][128 rows] stride 136
#define G_AL 2176
#define G_BH 4352     // [16 kd-pairs][128 cols] stride 136
#define G_BL 6528
#define G_WORDS 8704  // 34816 B static

__global__ void __launch_bounds__(256)
gemm_tc(const float* __restrict__ A, const float* __restrict__ W,
        const float* __restrict__ bias, float* __restrict__ C,
        int M, int N, int K, float scale) {
    __shared__ float sm[G_WORDS];
    uint32_t* ahw = (uint32_t*)(sm + G_AH);
    uint32_t* alw = (uint32_t*)(sm + G_AL);
    uint32_t* bhw = (uint32_t*)(sm + G_BH);
    uint32_t* blw = (uint32_t*)(sm + G_BL);

    const int bm = blockIdx.x * 128, bn = blockIdx.y * 128;
    const int tid = threadIdx.x;
    const int warp = tid >> 5, lane = tid & 31;
    const int g = lane >> 2, qd = lane & 3;
    const int r0 = warp * 16 + g;

    float o[16][4];
#pragma unroll
    for (int nt = 0; nt < 16; nt++)
#pragma unroll
        for (int j = 0; j < 4; j++) o[nt][j] = 0.f;

    for (int k0 = 0; k0 < K; k0 += 32) {
        __syncthreads();
        // stage A chunk: COALESCED (16 consecutive threads = one row's 128B)
#pragma unroll
        for (int i = 0; i < 8; i++) {
            int idx = tid + i * 256;
            int wp = idx & 15, r = idx >> 4;
            float2 v = *(const float2*)&A[(size_t)(bm + r) * K + k0 + 2 * wp];
            float h0 = bfhi(v.x), h1 = bfhi(v.y);
            ahw[wp * 136 + r] = bfpack(h0, h1);
            alw[wp * 136 + r] = bfpack(v.x - h0, v.y - h1);
        }
        // stage B chunk: already coalesced (consecutive n)
#pragma unroll
        for (int i = 0; i < 8; i++) {
            int idx = tid + i * 256;
            int wp = idx >> 7, n = idx & 127;
            float x0 = W[(size_t)(k0 + 2 * wp) * N + bn + n];
            float x1 = W[(size_t)(k0 + 2 * wp + 1) * N + bn + n];
            float h0 = bfhi(x0), h1 = bfhi(x1);
            bhw[wp * 136 + n] = bfpack(h0, h1);
            blw[wp * 136 + n] = bfpack(x0 - h0, x1 - h1);
        }
        __syncthreads();

        uint32_t aH[2][4], aL[2][4];
#pragma unroll
        for (int kst = 0; kst < 2; kst++) {
            int ba = (kst * 8 + qd) * 136 + r0;
            aH[kst][0] = ahw[ba];            aH[kst][1] = ahw[ba + 8];
            aH[kst][2] = ahw[ba + 4 * 136];  aH[kst][3] = ahw[ba + 4 * 136 + 8];
            aL[kst][0] = alw[ba];            aL[kst][1] = alw[ba + 8];
            aL[kst][2] = alw[ba + 4 * 136];  aL[kst][3] = alw[ba + 4 * 136 + 8];
        }
#pragma unroll
        for (int nt = 0; nt < 16; nt++) {
#pragma unroll
            for (int kst = 0; kst < 2; kst++) {
                uint32_t bH[2], bL[2];
                int ba = (kst * 8 + qd) * 136 + nt * 8 + g;
                bH[0] = bhw[ba]; bH[1] = bhw[ba + 4 * 136];
                bL[0] = blw[ba]; bL[1] = blw[ba + 4 * 136];
                mma_bf16(o[nt], aH[kst], bH);
                mma_bf16(o[nt], aH[kst], bL);
                mma_bf16(o[nt], aL[kst], bH);
            }
        }
    }

    // epilogue
#pragma unroll
    for (int nt = 0; nt < 16; nt++) {
        int col = bn + nt * 8 + qd * 2;
        float b0 = 0.f, b1 = 0.f;
        if (bias) { b0 = bias[col]; b1 = bias[col + 1]; }
        *(float2*)&C[(size_t)(bm + r0) * N + col] =
            make_float2(o[nt][0] * scale + b0, o[nt][1] * scale + b1);
        *(float2*)&C[(size_t)(bm + r0 + 8) * N + col] =
            make_float2(o[nt][2] * scale + b0, o[nt][3] * scale + b1);
    }
}

// ---------------- norm kernels (softmax shift bound) ----------------
__global__ void qnorm_kernel(const float* __restrict__ q, float* __restrict__ qn) {
    int t = blockIdx.x * 256 + threadIdx.x;
    int h = t & 7, bq = t >> 3;
    int b = bq >> 12, qq = bq & 4095;
    const float* p = q + (size_t)bq * INNER + h * DH;
    float s = 0.f;
#pragma unroll
    for (int i = 0; i < 8; i++) {
        float4 v = *(const float4*)(p + i * 4);
        s += v.x * v.x + v.y * v.y + v.z * v.z + v.w * v.w;
    }
    qn[((b * NH + h) * Qn) + qq] = sqrtf(s);
}

__global__ void knorm_kernel(const float* __restrict__ k, float* __restrict__ knm) {
    int bh = blockIdx.x;
    int b = bh >> 3, h = bh & 7;
    float mx = 0.f;
    for (int row = threadIdx.x; row < Kn; row += 256) {
        const float* p = k + ((size_t)(b * Kn) + row) * INNER + h * DH;
        float s = 0.f;
#pragma unroll
        for (int i = 0; i < 8; i++) {
            float4 v = *(const float4*)(p + i * 4);
            s += v.x * v.x + v.y * v.y + v.z * v.z + v.w * v.w;
        }
        mx = fmaxf(mx, s);
    }
    __shared__ float red[256];
    red[threadIdx.x] = mx;
    __syncthreads();
    for (int s = 128; s; s >>= 1) {
        if (threadIdx.x < s) red[threadIdx.x] = fmaxf(red[threadIdx.x], red[threadIdx.x + s]);
        __syncthreads();
    }
    if (threadIdx.x == 0) knm[bh] = sqrtf(red[0]);
}

// ---------------- single-pass fused attention + in-kernel weight normalize --
// q is pre-scaled by scaling*log2e, so scores are log2-domain: p = ex2(s - c).
// Writes RAW p to wout during the loop, then the CTA re-streams its own 2MB
// tile scaled by 1/l in the epilogue (overlaps with other CTAs' compute).
// grid = (Qn/128, NH, Bc), 256 threads (8 warps x 16 q-rows), chunk = 128 kk.
#define S_QH 0                    // [16 kd-pairs][128 rows] stride 136
#define S_QL 2176
#define S_KH 4352                 // [16 kd-pairs][128 cols] stride 136
#define S_KL 6528
#define S_VH 8704                 // [64 kk-pairs][32 d]     stride 40
#define S_VL 11264
#define S_IL 13824                // 1/l per row [128]
#define SM_WORDS 13952
#define SM_BYTES (SM_WORDS*4)     // 55808

__global__ void __launch_bounds__(256, 2)
fa_kernel(const float* __restrict__ qs, const float* __restrict__ ks,
          const float* __restrict__ vs, const float* __restrict__ qn,
          const float* __restrict__ knm,
          float* __restrict__ wout, float* __restrict__ qo) {
    extern __shared__ float sm[];
    uint32_t* qhw = (uint32_t*)(sm + S_QH);
    uint32_t* qlw = (uint32_t*)(sm + S_QL);
    uint32_t* khw = (uint32_t*)(sm + S_KH);
    uint32_t* klw = (uint32_t*)(sm + S_KL);
    uint32_t* vhw = (uint32_t*)(sm + S_VH);
    uint32_t* vlw = (uint32_t*)(sm + S_VL);
    float*    ilm = sm + S_IL;

    const int b = blockIdx.z, h = blockIdx.y, q0 = blockIdx.x * 128;
    const int tid = threadIdx.x;
    const int warp = tid >> 5, lane = tid & 31;
    const int g = lane >> 2, qd = lane & 3;
    const size_t bh = (size_t)(b * NH + h);

    // ---- stage Q tile: COALESCED (16 consecutive threads = one row) ----
#pragma unroll
    for (int i = 0; i < 8; i++) {
        int idx = tid + i * 256;
        int wp = idx & 15, r = idx >> 4;
        float2 v = *(const float2*)&qs[((size_t)(b * Qn) + q0 + r) * INNER + h * DH + 2 * wp];
        float h0 = bfhi(v.x), h1 = bfhi(v.y);
        qhw[wp * 136 + r] = bfpack(h0, h1);
        qlw[wp * 136 + r] = bfpack(v.x - h0, v.y - h1);
    }

    const int r0 = warp * 16 + g;
    float cp0, cp1;
    {
        float km = knm[bh];
        cp0 = qn[bh * Qn + q0 + r0] * km;
        cp1 = qn[bh * Qn + q0 + r0 + 8] * km;
    }
    float l0 = 0.f, l1 = 0.f;

    __syncthreads();

    // ---- Q A-fragments (persist whole kernel) ----
    uint32_t aH[2][4], aL[2][4];
#pragma unroll
    for (int kst = 0; kst < 2; kst++) {
        int ba = (kst * 8 + qd) * 136 + warp * 16 + g;
        aH[kst][0] = qhw[ba];            aH[kst][1] = qhw[ba + 8];
        aH[kst][2] = qhw[ba + 4 * 136];  aH[kst][3] = qhw[ba + 4 * 136 + 8];
        aL[kst][0] = qlw[ba];            aL[kst][1] = qlw[ba + 8];
        aL[kst][2] = qlw[ba + 4 * 136];  aL[kst][3] = qlw[ba + 4 * 136 + 8];
    }

    float o[4][4];
#pragma unroll
    for (int dt = 0; dt < 4; dt++)
#pragma unroll
        for (int j = 0; j < 4; j++) o[dt][j] = 0.f;

    for (int c = 0; c < Kn / 128; c++) {
        const int c0 = c * 128;
        __syncthreads();

        // ---- stage K chunk: COALESCED (16 consecutive threads = one row) ----
#pragma unroll
        for (int i = 0; i < 8; i++) {
            int idx = tid + i * 256;
            int wp = idx & 15, col = idx >> 4;
            float2 v = *(const float2*)&ks[((size_t)(b * Kn) + c0 + col) * INNER + h * DH + 2 * wp];
            float h0 = bfhi(v.x), h1 = bfhi(v.y);
            khw[wp * 136 + col] = bfpack(h0, h1);
            klw[wp * 136 + col] = bfpack(v.x - h0, v.y - h1);
        }
        // ---- stage V chunk (already coalesced: consecutive d) ----
#pragma unroll
        for (int i = 0; i < 8; i++) {
            int idx = tid + i * 256;
            int kp = idx >> 5, d = idx & 31;
            float x0 = vs[((size_t)(b * Kn) + c0 + 2 * kp) * INNER + h * DH + d];
            float x1 = vs[((size_t)(b * Kn) + c0 + 2 * kp + 1) * INNER + h * DH + d];
            float h0 = bfhi(x0), h1 = bfhi(x1);
            vhw[kp * 40 + d] = bfpack(h0, h1);
            vlw[kp * 40 + d] = bfpack(x0 - h0, x1 - h1);
        }
        __syncthreads();

#pragma unroll 2
        for (int ksb = 0; ksb < 8; ksb++) {
            uint32_t pH[4], pL[4];
#pragma unroll
            for (int t = 0; t < 2; t++) {
                const int nt = ksb * 2 + t;
                float cacc[4] = {0.f, 0.f, 0.f, 0.f};
#pragma unroll
                for (int kst = 0; kst < 2; kst++) {
                    uint32_t bH[2], bL[2];
                    int ba = (kst * 8 + qd) * 136 + nt * 8 + g;
                    bH[0] = khw[ba]; bH[1] = khw[ba + 4 * 136];
                    bL[0] = klw[ba]; bL[1] = klw[ba + 4 * 136];
                    mma_bf16(cacc, aH[kst], bH);
                    mma_bf16(cacc, aH[kst], bL);
                    mma_bf16(cacc, aL[kst], bH);
                }
                float p0 = ex2(cacc[0] - cp0);
                float p1 = ex2(cacc[1] - cp0);
                float p2 = ex2(cacc[2] - cp1);
                float p3 = ex2(cacc[3] - cp1);
                l0 += p0 + p1;
                l1 += p2 + p3;
                // raw weights (normalized in the fused epilogue below)
                size_t wb = (bh * Qn + q0 + r0) * (size_t)Kn + c0 + nt * 8 + qd * 2;
                *(float2*)&wout[wb] = make_float2(p0, p1);
                *(float2*)&wout[wb + (size_t)8 * Kn] = make_float2(p2, p3);
                // repack P into A-fragments
                float h0 = bfhi(p0), h1 = bfhi(p1);
                float h2 = bfhi(p2), h3 = bfhi(p3);
                pH[2 * t + 0] = bfpack(h0, h1);
                pH[2 * t + 1] = bfpack(h2, h3);
                pL[2 * t + 0] = bfpack(p0 - h0, p1 - h1);
                pL[2 * t + 1] = bfpack(p2 - h2, p3 - h3);
            }
            // ---- PV: O += P * V over this kk-block ----
#pragma unroll
            for (int dt = 0; dt < 4; dt++) {
                uint32_t bH[2], bL[2];
                int ba = (ksb * 8 + qd) * 40 + dt * 8 + g;
                bH[0] = vhw[ba]; bH[1] = vhw[ba + 4 * 40];
                bL[0] = vlw[ba]; bL[1] = vlw[ba + 4 * 40];
                mma_bf16(o[dt], pH, bH);
                mma_bf16(o[dt], pH, bL);
                mma_bf16(o[dt], pL, bH);
            }
        }
    }

    // ---- reduce l over the 4 qd lanes; normalize O; share 1/l ----
    l0 += __shfl_xor_sync(0xffffffffu, l0, 1);
    l0 += __shfl_xor_sync(0xffffffffu, l0, 2);
    l1 += __shfl_xor_sync(0xffffffffu, l1, 1);
    l1 += __shfl_xor_sync(0xffffffffu, l1, 2);
    float il0 = 1.0f / l0, il1 = 1.0f / l1;
    if (qd == 0) {
        ilm[r0] = il0;
        ilm[r0 + 8] = il1;
    }
    float* op0 = qo + ((size_t)(b * Qn) + q0 + r0) * INNER + h * DH;
    float* op1 = qo + ((size_t)(b * Qn) + q0 + r0 + 8) * INNER + h * DH;
#pragma unroll
    for (int dt = 0; dt < 4; dt++) {
        *(float2*)&op0[dt * 8 + qd * 2] = make_float2(o[dt][0] * il0, o[dt][1] * il0);
        *(float2*)&op1[dt * 8 + qd * 2] = make_float2(o[dt][2] * il1, o[dt][3] * il1);
    }
    __syncthreads();   // orders this CTA's weight STGs + ilm before re-read

    // ---- fused normalize of this CTA's contiguous 2MB weights tile ----
    {
        float* wt = wout + (bh * Qn + q0) * (size_t)Kn;
        for (int i = tid; i < 128 * 1024; i += 256) {
            float il = ilm[i >> 10];          // broadcast within warp
            float4 v = *(float4*)&wt[(size_t)i * 4];
            v.x *= il; v.y *= il; v.z *= il; v.w *= il;
            __stcs((float4*)&wt[(size_t)i * 4], v);   // streaming: no re-use
        }
    }
}

// ---------------- launch ----------------
extern "C" void kernel_launch(void* const* d_in, const int* in_sizes, int n_in,
                              void* d_out, int out_size) {
    const float* query = (const float*)d_in[0];
    const float* key   = (const float*)d_in[1];
    const float* value = (const float*)d_in[2];
    const float* Wq    = (const float*)d_in[3];
    const float* Wk    = (const float*)d_in[4];
    const float* Wv    = (const float*)d_in[5];
    const float* Wo    = (const float*)d_in[6];
    const float* bo    = (const float*)d_in[7];

    float* out_attn = (float*)d_out;                       // [B,Q,512]
    float* out_w    = (float*)d_out + (size_t)Bc*Qn*DQ;    // [B,H,Q,K]

    float *qs, *ksp, *vsp, *qop, *qnp, *knp;
    cudaGetSymbolAddress((void**)&qs,  g_qs);
    cudaGetSymbolAddress((void**)&ksp, g_ks);
    cudaGetSymbolAddress((void**)&vsp, g_vs);
    cudaGetSymbolAddress((void**)&qop, g_qo);
    cudaGetSymbolAddress((void**)&qnp, g_qn);
    cudaGetSymbolAddress((void**)&knp, g_knm);

    const int M = Bc * Qn;          // 8192
    // 1/sqrt(32) * log2(e): scores land in log2 domain -> ex2 in fa_kernel
    const float scaling = 0.17677669529663687f * 1.4426950408889634f;

    // 1) projections (tensor cores, bf16x3, 128x128 tiles)
    {
        dim3 grid(M / 128, INNER / 128);
        gemm_tc<<<grid, 256>>>(query, Wq, nullptr, qs,  M, INNER, DQ, scaling);
        gemm_tc<<<grid, 256>>>(key,   Wk, nullptr, ksp, M, INNER, DQ, 1.f);
        gemm_tc<<<grid, 256>>>(value, Wv, nullptr, vsp, M, INNER, DQ, 1.f);
    }
    // 2) softmax shift bound: c = ||q'|| * max||k||  (log2 domain via q scale)
    {
        qnorm_kernel<<<Bc * Qn * NH / 256, 256>>>(qs, qnp);
        knorm_kernel<<<Bc * NH, 256>>>(ksp, knp);
    }
    // 3) single-pass attention: raw weights + l + O, fused in-place normalize
    {
        cudaFuncSetAttribute(fa_kernel, cudaFuncAttributeMaxDynamicSharedMemorySize, SM_BYTES);
        dim3 grid(Qn / 128, NH, Bc);
        fa_kernel<<<grid, 256, SM_BYTES>>>(qs, ksp, vsp, qnp, knp, out_w, qop);
    }
    // 4) output projection + bias (tensor cores, bf16x3, 128x128 tiles)
    {
        dim3 grid(M / 128, DQ / 128);
        gemm_tc<<<grid, 256>>>(qop, Wo, bo, out_attn, M, DQ, INNER, 1.f);
    }
}